// round 7
// baseline (speedup 1.0000x reference)
#include <cuda_runtime.h>
#include <math.h>
#include <stdint.h>

#define BQ    32
#define CIN   128
#define LIN   1024
#define NE    4
#define COUT  128
#define KW    64
#define LOUT  961          // 1024 - 64 + 1
#define NTILE 112
#define NTILES 9           // 9*112 = 1008 >= 961; 288 CTAs ~ 97% of 2 waves
#define SWPAD 36           // W pair-row stride (words): banks distinct for frags
#define WNDW  176          // x window: NTILE + KW - 1 = 175, rounded up

// ---------------- scratch (device globals: no allocation allowed) ----------
__device__ float g_gatex[BQ * CIN];
__device__ int   g_sel [BQ * 2];
__device__ float g_selw[BQ * 2];

// ---------------- helpers -------------------------------------------------
__device__ __forceinline__ uint32_t pack_f16x2(float lo, float hi) {
    uint32_t r;
    asm("cvt.rn.f16x2.f32 %0, %1, %2;" : "=r"(r) : "f"(hi), "f"(lo));
    return r;
}

__device__ __forceinline__ void mma_f16(float* c,
                                        uint32_t a0, uint32_t a1, uint32_t a2, uint32_t a3,
                                        uint32_t b0, uint32_t b1) {
    asm volatile("mma.sync.aligned.m16n8k16.row.col.f32.f16.f16.f32 "
                 "{%0,%1,%2,%3}, {%4,%5,%6,%7}, {%8,%9}, {%0,%1,%2,%3};"
                 : "+f"(c[0]), "+f"(c[1]), "+f"(c[2]), "+f"(c[3])
                 : "r"(a0), "r"(a1), "r"(a2), "r"(a3), "r"(b0), "r"(b1));
}

// ---------------- kernel 1: gate_x = mean over L (warp per row) -----------
__global__ void k_gatex(const float* __restrict__ x) {
    int row  = blockIdx.x * 4 + (threadIdx.x >> 5);   // (b, c) flattened
    int lane = threadIdx.x & 31;
    const float4* xp = (const float4*)(x + (size_t)row * LIN);
    float s = 0.f;
#pragma unroll
    for (int k = 0; k < 8; ++k) {
        float4 v = xp[lane + k * 32];
        s += (v.x + v.y) + (v.z + v.w);
    }
#pragma unroll
    for (int off = 16; off; off >>= 1) s += __shfl_down_sync(0xffffffffu, s, off);
    if (lane == 0) g_gatex[row] = s * (1.0f / (float)LIN);
}

// ---------------- kernel 2: gating, top-k, loss ---------------------------
__device__ __forceinline__ float cv_sq4(const float* w) {
    float mn = 0.25f * (w[0] + w[1] + w[2] + w[3]);
    float s = 0.f;
#pragma unroll
    for (int e = 0; e < 4; ++e) { float d = w[e] - mn; s += d * d; }
    s *= (1.0f / 3.0f);                    // ddof = 1
    return s / (mn * mn + 1e-10f);
}

__global__ void k_gate(const float* __restrict__ noise,
                       const float* __restrict__ w_gate,
                       const float* __restrict__ w_noise,
                       float* __restrict__ out, int loss_idx)
{
    int b = threadIdx.x;                   // 32 threads, one per batch row
    float clean[NE] = {0.f, 0.f, 0.f, 0.f};
    float raw[NE]   = {0.f, 0.f, 0.f, 0.f};
    for (int c = 0; c < CIN; ++c) {
        float gx = g_gatex[b * CIN + c];
#pragma unroll
        for (int e = 0; e < NE; ++e) {
            clean[e] = fmaf(gx, w_gate[c * NE + e],  clean[e]);
            raw[e]   = fmaf(gx, w_noise[c * NE + e], raw[e]);
        }
    }
    float nstd[NE], noisy[NE], sm[NE];
    float m = -1e30f;
#pragma unroll
    for (int e = 0; e < NE; ++e) {
        float r  = raw[e];
        float sp = (r > 20.f) ? r : log1pf(expf(r));   // softplus
        nstd[e]  = sp + 0.01f;                          // NOISE_EPS
        noisy[e] = clean[e] + noise[b * NE + e] * nstd[e];
        m = fmaxf(m, noisy[e]);
    }
    float ssum = 0.f;
#pragma unroll
    for (int e = 0; e < NE; ++e) { sm[e] = expf(noisy[e] - m); ssum += sm[e]; }
    float inv = 1.f / ssum;
#pragma unroll
    for (int e = 0; e < NE; ++e) sm[e] *= inv;

    int   idx[4] = {0, 1, 2, 3};
    float v[4]   = {sm[0], sm[1], sm[2], sm[3]};
#pragma unroll
    for (int a = 0; a < 3; ++a)
#pragma unroll
        for (int q = a + 1; q < 4; ++q)
            if (v[q] > v[a]) {
                float tv = v[a]; v[a] = v[q]; v[q] = tv;
                int   ti = idx[a]; idx[a] = idx[q]; idx[q] = ti;
            }

    float e1 = expf(v[1] - v[0]);
    float gs = 1.f + e1;
    float g0 = 1.f / gs;
    float g1 = e1 / gs;
    g_sel [b * 2 + 0] = idx[0];  g_sel [b * 2 + 1] = idx[1];
    g_selw[b * 2 + 0] = g0;      g_selw[b * 2 + 1] = g1;

    float gates[4] = {0.f, 0.f, 0.f, 0.f};
    gates[idx[0]] = g0;
    gates[idx[1]] = g1;

    float thr_in  = v[2];
    float thr_out = v[1];
    float loadc[4];
#pragma unroll
    for (int e = 0; e < NE; ++e) {
        bool  is_in = noisy[e] > thr_in;
        float thr   = is_in ? thr_in : thr_out;
        float z     = (clean[e] - thr) / nstd[e];
        loadc[e]    = 0.5f * (1.f + erff(z * 0.70710678118654752f));
    }

    float imp[4], ld[4];
#pragma unroll
    for (int e = 0; e < NE; ++e) {
        float a = gates[e], l2 = loadc[e];
        for (int off = 16; off; off >>= 1) {
            a  += __shfl_down_sync(0xffffffffu, a,  off);
            l2 += __shfl_down_sync(0xffffffffu, l2, off);
        }
        imp[e] = a; ld[e] = l2;
    }
    if (b == 0)
        out[loss_idx] = 0.01f * (cv_sq4(imp) + cv_sq4(ld));
}

// ---------------- kernel 3: fp16 tensor-core sparse conv experts ----------
// grid: (NTILES=9, BQ=32) = 288 CTAs, 512 threads (16 warps), 1 CTA/SM.
// CTA tile: M=128 (Cout) x N=112 (l). Warp w: m-rows [(w&7)*16, +16),
// n-half (w>>3)*56. Per channel: 64 taps = 4 k16-steps of mma m16n8k16 f16.
// DOUBLE-BUFFERED staging: channel k lives in buffer/regset k&1. At iter c:
// STS(c+1) into the idle buffer (drained by the end barrier, hidden under
// HMMA), LDG(c+2) into the freed regset, ONE __syncthreads per channel.
__global__ void __launch_bounds__(512, 1)
k_conv(const float* __restrict__ x,
       const float* __restrict__ W1,
       const float* __restrict__ b1,
       const float* __restrict__ W2,
       const float* __restrict__ b2,
       float* __restrict__ out)
{
    __shared__ __align__(16) uint32_t sw[2][COUT * SWPAD]; // f16x2 pairs, 2x18.4KB
    __shared__ uint32_t sxp[2][WNDW];                      // paired x window f16x2
    __shared__ float sred[16][4][28];                      // epilogue partials
    __shared__ float sz[2][NTILE];
    __shared__ float ysum[2][NTILE];
    __shared__ float sW2[2][COUT];
    __shared__ float sb1[COUT];

    const int b    = blockIdx.y;
    const int l0   = blockIdx.x * NTILE;
    const int tid  = threadIdx.x;
    const int warp = tid >> 5;
    const int lane = tid & 31;
    const int g    = lane >> 2;
    const int t4   = lane & 3;
    const int m0   = (warp & 7) * 16;
    const int nhalf= warp >> 3;
    const int rlo  = m0 + g;
    const int rhi  = m0 + g + 8;
    const int so   = tid >> 4;          // W staging: o base (o = so + r*32)
    const int sq   = tid & 15;          // W staging: tap quad [4sq, 4sq+4)

    const float* xb = x + (size_t)b * CIN * LIN;

    if (tid < 2 * NTILE) {
        int t = tid >= NTILE;
        ysum[t][tid - t * NTILE] = 0.f;
    }

    for (int slot = 0; slot < 2; ++slot) {
        const int   e  = g_sel [b * 2 + slot];
        const float gw = g_selw[b * 2 + slot];
        const float* W1e = W1 + (size_t)e * COUT * CIN * KW;

        if (tid < 2 * COUT) sW2[tid >> 7][tid & 127] = W2[e * 2 * COUT + tid];
        if (tid < COUT)     sb1[tid] = b1[e * COUT + tid];

        float acc[7][4];
#pragma unroll
        for (int i = 0; i < 7; ++i)
#pragma unroll
            for (int j = 0; j < 4; ++j) acc[i][j] = 0.f;

        // two register staging sets: channel k -> set k&1
        float4 wreg[2][4];
        float  xra[2], xrb[2];

        // ---- pre-loop: LDG ch0 -> set0, STS ch0 -> buf0, LDG ch1 -> set1 --
#pragma unroll
        for (int r = 0; r < 4; ++r) {
            int o = so + r * 32;
            wreg[0][r] = *(const float4*)(W1e + ((size_t)o * CIN + 0) * KW + sq * 4);
        }
        if (tid < WNDW) {
            int l = l0 + tid;
            xra[0] = (l < LIN)     ? xb[l]     : 0.f;
            xrb[0] = (l + 1 < LIN) ? xb[l + 1] : 0.f;   // same L1 line
        }
#pragma unroll
        for (int r = 0; r < 4; ++r) {
            int o = so + r * 32;
            uint2 u;
            u.x = pack_f16x2(wreg[0][r].x, wreg[0][r].y);
            u.y = pack_f16x2(wreg[0][r].z, wreg[0][r].w);
            *(uint2*)&sw[0][o * SWPAD + sq * 2] = u;
        }
        if (tid < WNDW) sxp[0][tid] = pack_f16x2(xra[0], xrb[0]);
#pragma unroll
        for (int r = 0; r < 4; ++r) {
            int o = so + r * 32;
            wreg[1][r] = *(const float4*)(W1e + ((size_t)o * CIN + 1) * KW + sq * 4);
        }
        if (tid < WNDW) {
            int l = l0 + tid;
            const float* xc = xb + LIN;
            xra[1] = (l < LIN)     ? xc[l]     : 0.f;
            xrb[1] = (l + 1 < LIN) ? xc[l + 1] : 0.f;
        }
        __syncthreads();                 // buf0 staged & visible

        for (int c = 0; c < CIN; ++c) {
            const int cur = c & 1;
            const int nxt = cur ^ 1;

            // STS channel c+1 (regs loaded last iter) into idle buffer;
            // drained by the barrier at loop end, hidden under the MMAs.
            if (c + 1 < CIN) {
#pragma unroll
                for (int r = 0; r < 4; ++r) {
                    int o = so + r * 32;
                    uint2 u;
                    u.x = pack_f16x2(wreg[nxt][r].x, wreg[nxt][r].y);
                    u.y = pack_f16x2(wreg[nxt][r].z, wreg[nxt][r].w);
                    *(uint2*)&sw[nxt][o * SWPAD + sq * 2] = u;
                }
                if (tid < WNDW) sxp[nxt][tid] = pack_f16x2(xra[nxt], xrb[nxt]);
            }
            // LDG channel c+2 into the regset just freed (set c&1)
            if (c + 2 < CIN) {
                const float* xc = xb + (size_t)(c + 2) * LIN;
#pragma unroll
                for (int r = 0; r < 4; ++r) {
                    int o = so + r * 32;
                    wreg[cur][r] = *(const float4*)(W1e + ((size_t)o * CIN + (c + 2)) * KW + sq * 4);
                }
                if (tid < WNDW) {
                    int l = l0 + tid;
                    xra[cur] = (l < LIN)     ? xc[l]     : 0.f;
                    xrb[cur] = (l + 1 < LIN) ? xc[l + 1] : 0.f;
                }
            }

            // B pairs: P[j] = sxp[cur][bbase + 8j], one LDS.32 each.
            uint32_t P[14];
            const int bbase = nhalf * 56 + g + 2 * t4;
            const uint32_t* sxc = sxp[cur];
#pragma unroll
            for (int j = 0; j < 14; ++j) P[j] = sxc[bbase + 8 * j];

            const uint32_t* swc = sw[cur];
#pragma unroll
            for (int kk = 0; kk < 4; ++kk) {
                const uint32_t* swr = &swc[kk * 8 + t4];
                uint32_t a0 = swr[rlo * SWPAD];
                uint32_t a1 = swr[rhi * SWPAD];
                uint32_t a2 = swr[rlo * SWPAD + 4];
                uint32_t a3 = swr[rhi * SWPAD + 4];
#pragma unroll
                for (int nb = 0; nb < 7; ++nb) {
                    int s = 2 * kk + nb;
                    mma_f16(acc[nb], a0, a1, a2, a3, P[s], P[s + 1]);
                }
            }
            __syncthreads();             // staging of c+1 visible; buf reuse safe
        }

        // ---- epilogue: bias + relu + W2 partials, reduce over Cout ----
        float b1lo = sb1[rlo], b1hi = sb1[rhi];
        float w2lo0 = sW2[0][rlo], w2hi0 = sW2[0][rhi];
        float w2lo1 = sW2[1][rlo], w2hi1 = sW2[1][rhi];
        float p[28];                    // [nb*4 + r*2 + t], r = col parity
#pragma unroll
        for (int nb = 0; nb < 7; ++nb) {
            float h00 = fmaxf(acc[nb][0] + b1lo, 0.f);   // (rlo, col even)
            float h01 = fmaxf(acc[nb][1] + b1lo, 0.f);   // (rlo, col odd)
            float h10 = fmaxf(acc[nb][2] + b1hi, 0.f);   // (rhi, col even)
            float h11 = fmaxf(acc[nb][3] + b1hi, 0.f);   // (rhi, col odd)
            p[nb * 4 + 0] = fmaf(w2lo0, h00, w2hi0 * h10);
            p[nb * 4 + 1] = fmaf(w2lo1, h00, w2hi1 * h10);
            p[nb * 4 + 2] = fmaf(w2lo0, h01, w2hi0 * h11);
            p[nb * 4 + 3] = fmaf(w2lo1, h01, w2hi1 * h11);
        }
        // reduce over g (8 lanes sharing t4)
#pragma unroll
        for (int j = 0; j < 28; ++j) {
            p[j] += __shfl_down_sync(0xffffffffu, p[j], 16);
            p[j] += __shfl_down_sync(0xffffffffu, p[j], 8);
            p[j] += __shfl_down_sync(0xffffffffu, p[j], 4);
        }
        if (lane < 4) {
#pragma unroll
            for (int j = 0; j < 28; ++j) sred[warp][lane][j] = p[j];
        }
        __syncthreads();

        // z[t][col]: sum 8 warps of the matching n-half
        if (tid < 2 * NTILE) {
            int t   = tid >= NTILE;
            int col = tid - t * NTILE;
            int nh  = col >= 56;
            int ch  = col - nh * 56;
            int nb  = ch >> 3;
            int tt4 = (ch >> 1) & 3;
            int r   = ch & 1;
            int pj  = nb * 4 + r * 2 + t;
            float z = b2[e * 2 + t];
#pragma unroll
            for (int w8 = 0; w8 < 8; ++w8) z += sred[nh * 8 + w8][tt4][pj];
            sz[t][col] = z;
        }
        __syncthreads();

        // 2-way softmax over t, gate-weighted accumulate
        if (tid < NTILE) {
            float z0 = sz[0][tid], z1 = sz[1][tid];
            float mm = fmaxf(z0, z1);
            float a0 = expf(z0 - mm), a1 = expf(z1 - mm);
            float is = 1.f / (a0 + a1);
            ysum[0][tid] += gw * a0 * is;
            ysum[1][tid] += gw * a1 * is;
        }
        __syncthreads();
    }

    if (tid < 2 * NTILE) {
        int t = tid >= NTILE, l = tid - t * NTILE;
        int gl = l0 + l;
        if (gl < LOUT)
            out[((size_t)b * 2 + t) * LOUT + gl] = ysum[t][l];
    }
}

// ---------------- launcher ------------------------------------------------
extern "C" void kernel_launch(void* const* d_in, const int* in_sizes, int n_in,
                              void* d_out, int out_size)
{
    const float* x       = (const float*)d_in[0];
    const float* noise   = (const float*)d_in[1];
    const float* w_gate  = (const float*)d_in[2];
    const float* w_noise = (const float*)d_in[3];
    const float* W1      = (const float*)d_in[4];
    const float* b1      = (const float*)d_in[5];
    const float* W2      = (const float*)d_in[6];
    const float* b2      = (const float*)d_in[7];
    float* out = (float*)d_out;

    k_gatex<<<BQ * CIN / 4, 128>>>(x);
    k_gate<<<1, 32>>>(noise, w_gate, w_noise, out, out_size - 1);
    dim3 grid(NTILES, BQ);
    k_conv<<<grid, 512>>>(x, W1, b1, W2, b2, out);
}

// round 8
// speedup vs baseline: 1.5686x; 1.5686x over previous
#include <cuda_runtime.h>
#include <math.h>
#include <stdint.h>

#define BQ    32
#define CIN   128
#define LIN   1024
#define NE    4
#define COUT  128
#define KW    64
#define LOUT  961          // 1024 - 64 + 1
#define NTILE 112
#define NTILES 9           // 9*112 = 1008 >= 961; 288 CTAs ~ 97% of 2 waves
#define SWPAD 36           // W pair-row stride (words): banks distinct for frags
#define WNDW  176          // x window: NTILE + KW - 1 = 175, rounded up

// ---------------- scratch (device globals: no allocation allowed) ----------
__device__ float g_gatex[BQ * CIN];
__device__ int   g_sel [BQ * 2];
__device__ float g_selw[BQ * 2];

// ---------------- helpers -------------------------------------------------
__device__ __forceinline__ uint32_t pack_f16x2(float lo, float hi) {
    uint32_t r;
    asm("cvt.rn.f16x2.f32 %0, %1, %2;" : "=r"(r) : "f"(hi), "f"(lo));
    return r;
}

__device__ __forceinline__ void mma_f16(float* c,
                                        uint32_t a0, uint32_t a1, uint32_t a2, uint32_t a3,
                                        uint32_t b0, uint32_t b1) {
    asm volatile("mma.sync.aligned.m16n8k16.row.col.f32.f16.f16.f32 "
                 "{%0,%1,%2,%3}, {%4,%5,%6,%7}, {%8,%9}, {%0,%1,%2,%3};"
                 : "+f"(c[0]), "+f"(c[1]), "+f"(c[2]), "+f"(c[3])
                 : "r"(a0), "r"(a1), "r"(a2), "r"(a3), "r"(b0), "r"(b1));
}

// ---------------- kernel 1: gate_x = mean over L (warp per row) -----------
__global__ void k_gatex(const float* __restrict__ x) {
    int row  = blockIdx.x * 4 + (threadIdx.x >> 5);   // (b, c) flattened
    int lane = threadIdx.x & 31;
    const float4* xp = (const float4*)(x + (size_t)row * LIN);
    float s = 0.f;
#pragma unroll
    for (int k = 0; k < 8; ++k) {
        float4 v = xp[lane + k * 32];
        s += (v.x + v.y) + (v.z + v.w);
    }
#pragma unroll
    for (int off = 16; off; off >>= 1) s += __shfl_down_sync(0xffffffffu, s, off);
    if (lane == 0) g_gatex[row] = s * (1.0f / (float)LIN);
}

// ---------------- kernel 2: gating, top-k, loss ---------------------------
__device__ __forceinline__ float cv_sq4(const float* w) {
    float mn = 0.25f * (w[0] + w[1] + w[2] + w[3]);
    float s = 0.f;
#pragma unroll
    for (int e = 0; e < 4; ++e) { float d = w[e] - mn; s += d * d; }
    s *= (1.0f / 3.0f);                    // ddof = 1
    return s / (mn * mn + 1e-10f);
}

__global__ void k_gate(const float* __restrict__ noise,
                       const float* __restrict__ w_gate,
                       const float* __restrict__ w_noise,
                       float* __restrict__ out, int loss_idx)
{
    int b = threadIdx.x;                   // 32 threads, one per batch row
    float clean[NE] = {0.f, 0.f, 0.f, 0.f};
    float raw[NE]   = {0.f, 0.f, 0.f, 0.f};
    for (int c = 0; c < CIN; ++c) {
        float gx = g_gatex[b * CIN + c];
#pragma unroll
        for (int e = 0; e < NE; ++e) {
            clean[e] = fmaf(gx, w_gate[c * NE + e],  clean[e]);
            raw[e]   = fmaf(gx, w_noise[c * NE + e], raw[e]);
        }
    }
    float nstd[NE], noisy[NE], sm[NE];
    float m = -1e30f;
#pragma unroll
    for (int e = 0; e < NE; ++e) {
        float r  = raw[e];
        float sp = (r > 20.f) ? r : log1pf(expf(r));   // softplus
        nstd[e]  = sp + 0.01f;                          // NOISE_EPS
        noisy[e] = clean[e] + noise[b * NE + e] * nstd[e];
        m = fmaxf(m, noisy[e]);
    }
    float ssum = 0.f;
#pragma unroll
    for (int e = 0; e < NE; ++e) { sm[e] = expf(noisy[e] - m); ssum += sm[e]; }
    float inv = 1.f / ssum;
#pragma unroll
    for (int e = 0; e < NE; ++e) sm[e] *= inv;

    int   idx[4] = {0, 1, 2, 3};
    float v[4]   = {sm[0], sm[1], sm[2], sm[3]};
#pragma unroll
    for (int a = 0; a < 3; ++a)
#pragma unroll
        for (int q = a + 1; q < 4; ++q)
            if (v[q] > v[a]) {
                float tv = v[a]; v[a] = v[q]; v[q] = tv;
                int   ti = idx[a]; idx[a] = idx[q]; idx[q] = ti;
            }

    float e1 = expf(v[1] - v[0]);
    float gs = 1.f + e1;
    float g0 = 1.f / gs;
    float g1 = e1 / gs;
    g_sel [b * 2 + 0] = idx[0];  g_sel [b * 2 + 1] = idx[1];
    g_selw[b * 2 + 0] = g0;      g_selw[b * 2 + 1] = g1;

    float gates[4] = {0.f, 0.f, 0.f, 0.f};
    gates[idx[0]] = g0;
    gates[idx[1]] = g1;

    float thr_in  = v[2];
    float thr_out = v[1];
    float loadc[4];
#pragma unroll
    for (int e = 0; e < NE; ++e) {
        bool  is_in = noisy[e] > thr_in;
        float thr   = is_in ? thr_in : thr_out;
        float z     = (clean[e] - thr) / nstd[e];
        loadc[e]    = 0.5f * (1.f + erff(z * 0.70710678118654752f));
    }

    float imp[4], ld[4];
#pragma unroll
    for (int e = 0; e < NE; ++e) {
        float a = gates[e], l2 = loadc[e];
        for (int off = 16; off; off >>= 1) {
            a  += __shfl_down_sync(0xffffffffu, a,  off);
            l2 += __shfl_down_sync(0xffffffffu, l2, off);
        }
        imp[e] = a; ld[e] = l2;
    }
    if (b == 0)
        out[loss_idx] = 0.01f * (cv_sq4(imp) + cv_sq4(ld));
}

// ---------------- kernel 3: fp16 tensor-core sparse conv experts ----------
// grid: (NTILES=9, BQ=32) = 288 CTAs, 512 threads (16 warps), 1 CTA/SM.
// CTA tile: M=128 (Cout) x N=112 (l). Warp w: m-rows [(w&7)*16, +16),
// n-half (w>>3)*56. Per channel: 64 taps = 4 k16-steps of mma m16n8k16 f16.
// Double-buffered staging with the channel loop UNROLLED x2 so all buffer
// and staging-register indices are compile-time constants (R7's dynamic
// indexing demoted wreg[] to local memory — 1.8x regression). One barrier
// per channel; STS of the next channel drains at that barrier, hidden
// under the HMMA block.
__global__ void __launch_bounds__(512, 1)
k_conv(const float* __restrict__ x,
       const float* __restrict__ W1,
       const float* __restrict__ b1,
       const float* __restrict__ W2,
       const float* __restrict__ b2,
       float* __restrict__ out)
{
    __shared__ __align__(16) uint32_t sw[2][COUT * SWPAD]; // f16x2 pairs, 2x18.4KB
    __shared__ uint32_t sxp[2][WNDW];                      // paired x window f16x2
    __shared__ float sred[16][4][28];                      // epilogue partials
    __shared__ float sz[2][NTILE];
    __shared__ float ysum[2][NTILE];
    __shared__ float sW2[2][COUT];
    __shared__ float sb1[COUT];

    const int b    = blockIdx.y;
    const int l0   = blockIdx.x * NTILE;
    const int tid  = threadIdx.x;
    const int warp = tid >> 5;
    const int lane = tid & 31;
    const int g    = lane >> 2;
    const int t4   = lane & 3;
    const int m0   = (warp & 7) * 16;
    const int nhalf= warp >> 3;
    const int rlo  = m0 + g;
    const int rhi  = m0 + g + 8;
    const int so   = tid >> 4;          // W staging: o base (o = so + r*32)
    const int sq   = tid & 15;          // W staging: tap quad [4sq, 4sq+4)

    const float* xb = x + (size_t)b * CIN * LIN;
    const bool xact = (tid < WNDW);

    if (tid < 2 * NTILE) {
        int t = tid >= NTILE;
        ysum[t][tid - t * NTILE] = 0.f;
    }

    // staging helpers as macros: all indices compile-time constants
#define LDG_CH(SET, CH) do {                                                   \
        const float* xc_ = xb + (size_t)(CH) * LIN;                            \
        _Pragma("unroll")                                                      \
        for (int r_ = 0; r_ < 4; ++r_) {                                       \
            int o_ = so + r_ * 32;                                             \
            wreg##SET[r_] = *(const float4*)(W1e + ((size_t)o_ * CIN + (CH)) * KW + sq * 4); \
        }                                                                      \
        if (xact) {                                                            \
            int l_ = l0 + tid;                                                 \
            xra##SET = (l_ < LIN)     ? xc_[l_]     : 0.f;                     \
            xrb##SET = (l_ + 1 < LIN) ? xc_[l_ + 1] : 0.f;                     \
        }                                                                      \
    } while (0)

#define STS_CH(SET) do {                                                       \
        _Pragma("unroll")                                                      \
        for (int r_ = 0; r_ < 4; ++r_) {                                       \
            int o_ = so + r_ * 32;                                             \
            uint2 u_;                                                          \
            u_.x = pack_f16x2(wreg##SET[r_].x, wreg##SET[r_].y);               \
            u_.y = pack_f16x2(wreg##SET[r_].z, wreg##SET[r_].w);               \
            *(uint2*)&sw[SET][o_ * SWPAD + sq * 2] = u_;                       \
        }                                                                      \
        if (xact) sxp[SET][tid] = pack_f16x2(xra##SET, xrb##SET);              \
    } while (0)

#define MMA_CH(BUF) do {                                                       \
        uint32_t P_[14];                                                       \
        const int bbase_ = nhalf * 56 + g + 2 * t4;                            \
        const uint32_t* sxc_ = sxp[BUF];                                       \
        _Pragma("unroll")                                                      \
        for (int j_ = 0; j_ < 14; ++j_) P_[j_] = sxc_[bbase_ + 8 * j_];        \
        const uint32_t* swc_ = sw[BUF];                                        \
        _Pragma("unroll")                                                      \
        for (int kk_ = 0; kk_ < 4; ++kk_) {                                    \
            const uint32_t* swr_ = &swc_[kk_ * 8 + t4];                        \
            uint32_t a0_ = swr_[rlo * SWPAD];                                  \
            uint32_t a1_ = swr_[rhi * SWPAD];                                  \
            uint32_t a2_ = swr_[rlo * SWPAD + 4];                              \
            uint32_t a3_ = swr_[rhi * SWPAD + 4];                              \
            _Pragma("unroll")                                                  \
            for (int nb_ = 0; nb_ < 7; ++nb_) {                                \
                int s_ = 2 * kk_ + nb_;                                        \
                mma_f16(acc[nb_], a0_, a1_, a2_, a3_, P_[s_], P_[s_ + 1]);     \
            }                                                                  \
        }                                                                      \
    } while (0)

    for (int slot = 0; slot < 2; ++slot) {
        const int   e  = g_sel [b * 2 + slot];
        const float gw = g_selw[b * 2 + slot];
        const float* W1e = W1 + (size_t)e * COUT * CIN * KW;

        if (tid < 2 * COUT) sW2[tid >> 7][tid & 127] = W2[e * 2 * COUT + tid];
        if (tid < COUT)     sb1[tid] = b1[e * COUT + tid];

        float acc[7][4];
#pragma unroll
        for (int i = 0; i < 7; ++i)
#pragma unroll
            for (int j = 0; j < 4; ++j) acc[i][j] = 0.f;

        // two register staging sets, named (compile-time) not indexed
        float4 wreg0[4], wreg1[4];
        float  xra0 = 0.f, xrb0 = 0.f, xra1 = 0.f, xrb1 = 0.f;

        // ---- pre-loop: LDG ch0 -> set0, STS set0 -> buf0, LDG ch1 -> set1 --
        LDG_CH(0, 0);
        STS_CH(0);
        LDG_CH(1, 1);
        __syncthreads();                 // buf0 staged & visible

        // channel loop, unrolled x2: even channel uses buf0, odd uses buf1
        for (int c = 0; c < CIN; c += 2) {
            // ---- even channel c: compute buf0; STS set1->buf1; LDG c+2->set0
            STS_CH(1);                   // channel c+1 -> buf1
            if (c + 2 < CIN) LDG_CH(0, c + 2);
            MMA_CH(0);
            __syncthreads();             // buf1 visible; buf0 free for re-stage

            // ---- odd channel c+1: compute buf1; STS set0->buf0; LDG c+3->set1
            if (c + 2 < CIN) STS_CH(0);  // channel c+2 -> buf0
            if (c + 3 < CIN) LDG_CH(1, c + 3);
            MMA_CH(1);
            __syncthreads();             // buf0 visible; buf1 free for re-stage
        }

        // ---- epilogue: bias + relu + W2 partials, reduce over Cout ----
        float b1lo = sb1[rlo], b1hi = sb1[rhi];
        float w2lo0 = sW2[0][rlo], w2hi0 = sW2[0][rhi];
        float w2lo1 = sW2[1][rlo], w2hi1 = sW2[1][rhi];
        float p[28];                    // [nb*4 + r*2 + t], r = col parity
#pragma unroll
        for (int nb = 0; nb < 7; ++nb) {
            float h00 = fmaxf(acc[nb][0] + b1lo, 0.f);   // (rlo, col even)
            float h01 = fmaxf(acc[nb][1] + b1lo, 0.f);   // (rlo, col odd)
            float h10 = fmaxf(acc[nb][2] + b1hi, 0.f);   // (rhi, col even)
            float h11 = fmaxf(acc[nb][3] + b1hi, 0.f);   // (rhi, col odd)
            p[nb * 4 + 0] = fmaf(w2lo0, h00, w2hi0 * h10);
            p[nb * 4 + 1] = fmaf(w2lo1, h00, w2hi1 * h10);
            p[nb * 4 + 2] = fmaf(w2lo0, h01, w2hi0 * h11);
            p[nb * 4 + 3] = fmaf(w2lo1, h01, w2hi1 * h11);
        }
        // reduce over g (8 lanes sharing t4)
#pragma unroll
        for (int j = 0; j < 28; ++j) {
            p[j] += __shfl_down_sync(0xffffffffu, p[j], 16);
            p[j] += __shfl_down_sync(0xffffffffu, p[j], 8);
            p[j] += __shfl_down_sync(0xffffffffu, p[j], 4);
        }
        if (lane < 4) {
#pragma unroll
            for (int j = 0; j < 28; ++j) sred[warp][lane][j] = p[j];
        }
        __syncthreads();

        // z[t][col]: sum 8 warps of the matching n-half
        if (tid < 2 * NTILE) {
            int t   = tid >= NTILE;
            int col = tid - t * NTILE;
            int nh  = col >= 56;
            int ch  = col - nh * 56;
            int nb  = ch >> 3;
            int tt4 = (ch >> 1) & 3;
            int r   = ch & 1;
            int pj  = nb * 4 + r * 2 + t;
            float z = b2[e * 2 + t];
#pragma unroll
            for (int w8 = 0; w8 < 8; ++w8) z += sred[nh * 8 + w8][tt4][pj];
            sz[t][col] = z;
        }
        __syncthreads();

        // 2-way softmax over t, gate-weighted accumulate
        if (tid < NTILE) {
            float z0 = sz[0][tid], z1 = sz[1][tid];
            float mm = fmaxf(z0, z1);
            float a0 = expf(z0 - mm), a1 = expf(z1 - mm);
            float is = 1.f / (a0 + a1);
            ysum[0][tid] += gw * a0 * is;
            ysum[1][tid] += gw * a1 * is;
        }
        __syncthreads();
    }

#undef LDG_CH
#undef STS_CH
#undef MMA_CH

    if (tid < 2 * NTILE) {
        int t = tid >= NTILE, l = tid - t * NTILE;
        int gl = l0 + l;
        if (gl < LOUT)
            out[((size_t)b * 2 + t) * LOUT + gl] = ysum[t][l];
    }
}

// ---------------- launcher ------------------------------------------------
extern "C" void kernel_launch(void* const* d_in, const int* in_sizes, int n_in,
                              void* d_out, int out_size)
{
    const float* x       = (const float*)d_in[0];
    const float* noise   = (const float*)d_in[1];
    const float* w_gate  = (const float*)d_in[2];
    const float* w_noise = (const float*)d_in[3];
    const float* W1      = (const float*)d_in[4];
    const float* b1      = (const float*)d_in[5];
    const float* W2      = (const float*)d_in[6];
    const float* b2      = (const float*)d_in[7];
    float* out = (float*)d_out;

    k_gatex<<<BQ * CIN / 4, 128>>>(x);
    k_gate<<<1, 32>>>(noise, w_gate, w_noise, out, out_size - 1);
    dim3 grid(NTILES, BQ);
    k_conv<<<grid, 512>>>(x, W1, b1, W2, b2, out);
}

// round 9
// speedup vs baseline: 1.8289x; 1.1659x over previous
#include <cuda_runtime.h>
#include <math.h>
#include <stdint.h>

#define BQ    32
#define CIN   128
#define LIN   1024
#define NE    4
#define COUT  128
#define KW    64
#define LOUT  961          // 1024 - 64 + 1
#define NTILE 112
#define NTILES 9           // 9*112 = 1008 >= 961; 288 CTAs ~ 97% of 2 waves
#define SWPAD 36           // W pair-row stride (words): LDSM rows on distinct banks
#define WNDW  176          // x window: NTILE + KW - 1 = 175, rounded up
#define NPAIR 32           // KW/2 f16x2 pairs per (o, c) row

// ---------------- scratch (device globals: no allocation allowed) ----------
__device__ float    g_gatex[BQ * CIN];
__device__ int      g_sel [BQ * 2];
__device__ float    g_selw[BQ * 2];
__device__ uint32_t g_w1h[NE * CIN * COUT * NPAIR];   // f16x2 W1, [e][c][o][p], 8.4MB

// ---------------- helpers -------------------------------------------------
__device__ __forceinline__ uint32_t pack_f16x2(float lo, float hi) {
    uint32_t r;
    asm("cvt.rn.f16x2.f32 %0, %1, %2;" : "=r"(r) : "f"(hi), "f"(lo));
    return r;
}

__device__ __forceinline__ uint32_t smem_u32(const void* p) {
    return (uint32_t)__cvta_generic_to_shared(p);
}

__device__ __forceinline__ void mma_f16(float* c,
                                        uint32_t a0, uint32_t a1, uint32_t a2, uint32_t a3,
                                        uint32_t b0, uint32_t b1) {
    asm volatile("mma.sync.aligned.m16n8k16.row.col.f32.f16.f16.f32 "
                 "{%0,%1,%2,%3}, {%4,%5,%6,%7}, {%8,%9}, {%0,%1,%2,%3};"
                 : "+f"(c[0]), "+f"(c[1]), "+f"(c[2]), "+f"(c[3])
                 : "r"(a0), "r"(a1), "r"(a2), "r"(a3), "r"(b0), "r"(b1));
}

// ---------------- kernel 0: W1 fp32 -> f16x2 pairs, [e][c][o][p] ----------
__global__ void k_wconv(const float* __restrict__ W1) {
    int w = blockIdx.x * 256 + threadIdx.x;   // [0, NE*CIN*COUT*NPAIR)
    int p = w & 31;
    int o = (w >> 5) & 127;
    int c = (w >> 12) & 127;
    int e = w >> 19;
    const float* src = W1 + (((size_t)(e * COUT + o) * CIN) + c) * KW + 2 * p;
    g_w1h[w] = pack_f16x2(src[0], src[1]);
}

// ---------------- kernel 1: gate_x = mean over L (warp per row) -----------
__global__ void k_gatex(const float* __restrict__ x) {
    int row  = blockIdx.x * 4 + (threadIdx.x >> 5);   // (b, c) flattened
    int lane = threadIdx.x & 31;
    const float4* xp = (const float4*)(x + (size_t)row * LIN);
    float s = 0.f;
#pragma unroll
    for (int k = 0; k < 8; ++k) {
        float4 v = xp[lane + k * 32];
        s += (v.x + v.y) + (v.z + v.w);
    }
#pragma unroll
    for (int off = 16; off; off >>= 1) s += __shfl_down_sync(0xffffffffu, s, off);
    if (lane == 0) g_gatex[row] = s * (1.0f / (float)LIN);
}

// ---------------- kernel 2: gating, top-k, loss ---------------------------
__device__ __forceinline__ float cv_sq4(const float* w) {
    float mn = 0.25f * (w[0] + w[1] + w[2] + w[3]);
    float s = 0.f;
#pragma unroll
    for (int e = 0; e < 4; ++e) { float d = w[e] - mn; s += d * d; }
    s *= (1.0f / 3.0f);                    // ddof = 1
    return s / (mn * mn + 1e-10f);
}

__global__ void k_gate(const float* __restrict__ noise,
                       const float* __restrict__ w_gate,
                       const float* __restrict__ w_noise,
                       float* __restrict__ out, int loss_idx)
{
    int b = threadIdx.x;                   // 32 threads, one per batch row
    float clean[NE] = {0.f, 0.f, 0.f, 0.f};
    float raw[NE]   = {0.f, 0.f, 0.f, 0.f};
    for (int c = 0; c < CIN; ++c) {
        float gx = g_gatex[b * CIN + c];
#pragma unroll
        for (int e = 0; e < NE; ++e) {
            clean[e] = fmaf(gx, w_gate[c * NE + e],  clean[e]);
            raw[e]   = fmaf(gx, w_noise[c * NE + e], raw[e]);
        }
    }
    float nstd[NE], noisy[NE], sm[NE];
    float m = -1e30f;
#pragma unroll
    for (int e = 0; e < NE; ++e) {
        float r  = raw[e];
        float sp = (r > 20.f) ? r : log1pf(expf(r));   // softplus
        nstd[e]  = sp + 0.01f;                          // NOISE_EPS
        noisy[e] = clean[e] + noise[b * NE + e] * nstd[e];
        m = fmaxf(m, noisy[e]);
    }
    float ssum = 0.f;
#pragma unroll
    for (int e = 0; e < NE; ++e) { sm[e] = expf(noisy[e] - m); ssum += sm[e]; }
    float inv = 1.f / ssum;
#pragma unroll
    for (int e = 0; e < NE; ++e) sm[e] *= inv;

    int   idx[4] = {0, 1, 2, 3};
    float v[4]   = {sm[0], sm[1], sm[2], sm[3]};
#pragma unroll
    for (int a = 0; a < 3; ++a)
#pragma unroll
        for (int q = a + 1; q < 4; ++q)
            if (v[q] > v[a]) {
                float tv = v[a]; v[a] = v[q]; v[q] = tv;
                int   ti = idx[a]; idx[a] = idx[q]; idx[q] = ti;
            }

    float e1 = expf(v[1] - v[0]);
    float gs = 1.f + e1;
    float g0 = 1.f / gs;
    float g1 = e1 / gs;
    g_sel [b * 2 + 0] = idx[0];  g_sel [b * 2 + 1] = idx[1];
    g_selw[b * 2 + 0] = g0;      g_selw[b * 2 + 1] = g1;

    float gates[4] = {0.f, 0.f, 0.f, 0.f};
    gates[idx[0]] = g0;
    gates[idx[1]] = g1;

    float thr_in  = v[2];
    float thr_out = v[1];
    float loadc[4];
#pragma unroll
    for (int e = 0; e < NE; ++e) {
        bool  is_in = noisy[e] > thr_in;
        float thr   = is_in ? thr_in : thr_out;
        float z     = (clean[e] - thr) / nstd[e];
        loadc[e]    = 0.5f * (1.f + erff(z * 0.70710678118654752f));
    }

    float imp[4], ld[4];
#pragma unroll
    for (int e = 0; e < NE; ++e) {
        float a = gates[e], l2 = loadc[e];
        for (int off = 16; off; off >>= 1) {
            a  += __shfl_down_sync(0xffffffffu, a,  off);
            l2 += __shfl_down_sync(0xffffffffu, l2, off);
        }
        imp[e] = a; ld[e] = l2;
    }
    if (b == 0)
        out[loss_idx] = 0.01f * (cv_sq4(imp) + cv_sq4(ld));
}

// ---------------- kernel 3: fp16 tensor-core sparse conv experts ----------
// grid: (NTILES=9, BQ=32) = 288 CTAs, 512 threads (16 warps), 1 CTA/SM.
// CTA tile: M=128 (Cout) x N=112 (l). Warp w: m-rows [(w&7)*16, +16),
// n-half (w>>3)*56. Per channel: 64 taps = 4 k16-steps of mma m16n8k16 f16.
// R5 single-buffer structure (two barriers/channel — measured fastest).
// A fragments via ldmatrix.m8n8.x4 (4 LDSM replace 16 LDS per warp-channel).
// W staged pre-converted to f16x2 by k_wconv (no CVT in loop, LDG bytes /2).
__global__ void __launch_bounds__(512, 1)
k_conv(const float* __restrict__ x,
       const float* __restrict__ b1,
       const float* __restrict__ W2,
       const float* __restrict__ b2,
       float* __restrict__ out)
{
    __shared__ __align__(16) uint32_t sw[COUT * SWPAD]; // f16x2 tap pairs, 18.4KB
    __shared__ uint32_t sxp[WNDW];                      // paired x window f16x2
    __shared__ float sred[16][4][28];                   // epilogue partials
    __shared__ float sz[2][NTILE];
    __shared__ float ysum[2][NTILE];
    __shared__ float sW2[2][COUT];
    __shared__ float sb1[COUT];

    const int b    = blockIdx.y;
    const int l0   = blockIdx.x * NTILE;
    const int tid  = threadIdx.x;
    const int warp = tid >> 5;
    const int lane = tid & 31;
    const int g    = lane >> 2;
    const int t4   = lane & 3;
    const int m0   = (warp & 7) * 16;
    const int nhalf= warp >> 3;
    const int rlo  = m0 + g;
    const int rhi  = m0 + g + 8;
    const int so   = tid >> 4;          // W staging: o base (o = so + r*32)
    const int sq   = tid & 15;          // W staging: pair duo [2sq, 2sq+2)

    // ldmatrix per-lane base address: row m0+(lane&15), word (lane>>4)*4
    const uint32_t a_base =
        smem_u32(&sw[(m0 + (lane & 15)) * SWPAD + ((lane >> 4) << 2)]);

    const float* xb = x + (size_t)b * CIN * LIN;

    if (tid < 2 * NTILE) {
        int t = tid >= NTILE;
        ysum[t][tid - t * NTILE] = 0.f;
    }

    for (int slot = 0; slot < 2; ++slot) {
        const int   e  = g_sel [b * 2 + slot];
        const float gw = g_selw[b * 2 + slot];
        const uint32_t* Whe = g_w1h + (size_t)e * (CIN * COUT * NPAIR);

        if (tid < 2 * COUT) sW2[tid >> 7][tid & 127] = W2[e * 2 * COUT + tid];
        if (tid < COUT)     sb1[tid] = b1[e * COUT + tid];

        float acc[7][4];
#pragma unroll
        for (int i = 0; i < 7; ++i)
#pragma unroll
            for (int j = 0; j < 4; ++j) acc[i][j] = 0.f;

        // ---- prefetch channel 0 (f16x2 pairs, no conversion needed) ----
        uint2 wreg[4];
        float xra = 0.f, xrb = 0.f;
#pragma unroll
        for (int r = 0; r < 4; ++r) {
            int o = so + r * 32;
            wreg[r] = *(const uint2*)(Whe + ((size_t)o * NPAIR) + 2 * sq);
        }
        if (tid < WNDW) {
            int l = l0 + tid;
            xra = (l < LIN)     ? xb[l]     : 0.f;
            xrb = (l + 1 < LIN) ? xb[l + 1] : 0.f;   // same L1 line
        }

        for (int c = 0; c < CIN; ++c) {
            __syncthreads();            // prior compute done reading sw/sxp
            // store channel c (already f16x2 — straight STS.64)
#pragma unroll
            for (int r = 0; r < 4; ++r) {
                int o = so + r * 32;
                *(uint2*)&sw[o * SWPAD + sq * 2] = wreg[r];
            }
            if (tid < WNDW) sxp[tid] = pack_f16x2(xra, xrb);
            __syncthreads();            // staging visible

            // prefetch channel c+1 (latency hidden under HMMA below)
            if (c + 1 < CIN) {
                const uint32_t* Whc = Whe + (size_t)(c + 1) * (COUT * NPAIR);
                const float*    xc  = xb + (size_t)(c + 1) * LIN;
#pragma unroll
                for (int r = 0; r < 4; ++r) {
                    int o = so + r * 32;
                    wreg[r] = *(const uint2*)(Whc + (size_t)o * NPAIR + 2 * sq);
                }
                if (tid < WNDW) {
                    int l = l0 + tid;
                    xra = (l < LIN)     ? xc[l]     : 0.f;
                    xrb = (l + 1 < LIN) ? xc[l + 1] : 0.f;
                }
            }

            // B pairs: P[j] = sxp[bbase + 8j], one LDS.32 each.
            uint32_t P[14];
            const int bbase = nhalf * 56 + g + 2 * t4;
#pragma unroll
            for (int j = 0; j < 14; ++j) P[j] = sxp[bbase + 8 * j];

#pragma unroll
            for (int kk = 0; kk < 4; ++kk) {
                uint32_t a0, a1, a2, a3;
                asm volatile(
                    "ldmatrix.sync.aligned.m8n8.x4.shared.b16 {%0,%1,%2,%3}, [%4];"
                    : "=r"(a0), "=r"(a1), "=r"(a2), "=r"(a3)
                    : "r"(a_base + kk * 32));
#pragma unroll
                for (int nb = 0; nb < 7; ++nb) {
                    int s = 2 * kk + nb;
                    mma_f16(acc[nb], a0, a1, a2, a3, P[s], P[s + 1]);
                }
            }
        }

        // ---- epilogue: bias + relu + W2 partials, reduce over Cout ----
        float b1lo = sb1[rlo], b1hi = sb1[rhi];
        float w2lo0 = sW2[0][rlo], w2hi0 = sW2[0][rhi];
        float w2lo1 = sW2[1][rlo], w2hi1 = sW2[1][rhi];
        float p[28];                    // [nb*4 + r*2 + t], r = col parity
#pragma unroll
        for (int nb = 0; nb < 7; ++nb) {
            float h00 = fmaxf(acc[nb][0] + b1lo, 0.f);   // (rlo, col even)
            float h01 = fmaxf(acc[nb][1] + b1lo, 0.f);   // (rlo, col odd)
            float h10 = fmaxf(acc[nb][2] + b1hi, 0.f);   // (rhi, col even)
            float h11 = fmaxf(acc[nb][3] + b1hi, 0.f);   // (rhi, col odd)
            p[nb * 4 + 0] = fmaf(w2lo0, h00, w2hi0 * h10);
            p[nb * 4 + 1] = fmaf(w2lo1, h00, w2hi1 * h10);
            p[nb * 4 + 2] = fmaf(w2lo0, h01, w2hi0 * h11);
            p[nb * 4 + 3] = fmaf(w2lo1, h01, w2hi1 * h11);
        }
        // reduce over g (8 lanes sharing t4)
#pragma unroll
        for (int j = 0; j < 28; ++j) {
            p[j] += __shfl_down_sync(0xffffffffu, p[j], 16);
            p[j] += __shfl_down_sync(0xffffffffu, p[j], 8);
            p[j] += __shfl_down_sync(0xffffffffu, p[j], 4);
        }
        __syncthreads();                // sred free from prior use
        if (lane < 4) {
#pragma unroll
            for (int j = 0; j < 28; ++j) sred[warp][lane][j] = p[j];
        }
        __syncthreads();

        // z[t][col]: sum 8 warps of the matching n-half
        if (tid < 2 * NTILE) {
            int t   = tid >= NTILE;
            int col = tid - t * NTILE;
            int nh  = col >= 56;
            int ch  = col - nh * 56;
            int nb  = ch >> 3;
            int tt4 = (ch >> 1) & 3;
            int r   = ch & 1;
            int pj  = nb * 4 + r * 2 + t;
            float z = b2[e * 2 + t];
#pragma unroll
            for (int w8 = 0; w8 < 8; ++w8) z += sred[nh * 8 + w8][tt4][pj];
            sz[t][col] = z;
        }
        __syncthreads();

        // 2-way softmax over t, gate-weighted accumulate
        if (tid < NTILE) {
            float z0 = sz[0][tid], z1 = sz[1][tid];
            float mm = fmaxf(z0, z1);
            float a0 = expf(z0 - mm), a1 = expf(z1 - mm);
            float is = 1.f / (a0 + a1);
            ysum[0][tid] += gw * a0 * is;
            ysum[1][tid] += gw * a1 * is;
        }
        __syncthreads();
    }

    if (tid < 2 * NTILE) {
        int t = tid >= NTILE, l = tid - t * NTILE;
        int gl = l0 + l;
        if (gl < LOUT)
            out[((size_t)b * 2 + t) * LOUT + gl] = ysum[t][l];
    }
}

// ---------------- launcher ------------------------------------------------
extern "C" void kernel_launch(void* const* d_in, const int* in_sizes, int n_in,
                              void* d_out, int out_size)
{
    const float* x       = (const float*)d_in[0];
    const float* noise   = (const float*)d_in[1];
    const float* w_gate  = (const float*)d_in[2];
    const float* w_noise = (const float*)d_in[3];
    const float* W1      = (const float*)d_in[4];
    const float* b1      = (const float*)d_in[5];
    const float* W2      = (const float*)d_in[6];
    const float* b2      = (const float*)d_in[7];
    float* out = (float*)d_out;

    k_wconv<<<NE * CIN * COUT * NPAIR / 256, 256>>>(W1);
    k_gatex<<<BQ * CIN / 4, 128>>>(x);
    k_gate<<<1, 32>>>(noise, w_gate, w_noise, out, out_size - 1);
    dim3 grid(NTILES, BQ);
    k_conv<<<grid, 512>>>(x, b1, W2, b2, out);
}

// round 10
// speedup vs baseline: 1.8852x; 1.0308x over previous
#include <cuda_runtime.h>
#include <math.h>
#include <stdint.h>

#define BQ    32
#define CIN   128
#define LIN   1024
#define NE    4
#define COUT  128
#define KW    64
#define LOUT  961          // 1024 - 64 + 1
#define NTILE 112
#define NTILES 9           // 9*112 = 1008 >= 961; 288 CTAs ~ 97% of 2 waves
#define SWPAD 36           // W pair-row stride (words): LDSM rows on distinct banks
#define WNDW  176          // x window: NTILE + KW - 1 = 175, rounded up
#define NPAIR 32           // KW/2 f16x2 pairs per (o, c) row

// ---------------- scratch (device globals: no allocation allowed) ----------
__device__ float    g_gatex[BQ * CIN];
__device__ int      g_sel [BQ * 2];
__device__ float    g_selw[BQ * 2];
__device__ uint32_t g_w1h[NE * CIN * COUT * NPAIR];   // f16x2 W1, [e][c][o][p], 8.4MB

// ---------------- helpers -------------------------------------------------
__device__ __forceinline__ uint32_t pack_f16x2(float lo, float hi) {
    uint32_t r;
    asm("cvt.rn.f16x2.f32 %0, %1, %2;" : "=r"(r) : "f"(hi), "f"(lo));
    return r;
}

__device__ __forceinline__ uint32_t smem_u32(const void* p) {
    return (uint32_t)__cvta_generic_to_shared(p);
}

__device__ __forceinline__ void mma_f16(float* c,
                                        uint32_t a0, uint32_t a1, uint32_t a2, uint32_t a3,
                                        uint32_t b0, uint32_t b1) {
    asm volatile("mma.sync.aligned.m16n8k16.row.col.f32.f16.f16.f32 "
                 "{%0,%1,%2,%3}, {%4,%5,%6,%7}, {%8,%9}, {%0,%1,%2,%3};"
                 : "+f"(c[0]), "+f"(c[1]), "+f"(c[2]), "+f"(c[3])
                 : "r"(a0), "r"(a1), "r"(a2), "r"(a3), "r"(b0), "r"(b1));
}

// ---------------- kernel 0: W1 fp32 -> f16x2 pairs, [e][c][o][p] ----------
__global__ void k_wconv(const float* __restrict__ W1) {
    int w = blockIdx.x * 256 + threadIdx.x;   // [0, NE*CIN*COUT*NPAIR)
    int p = w & 31;
    int o = (w >> 5) & 127;
    int c = (w >> 12) & 127;
    int e = w >> 19;
    const float* src = W1 + (((size_t)(e * COUT + o) * CIN) + c) * KW + 2 * p;
    g_w1h[w] = pack_f16x2(src[0], src[1]);
}

// ---------------- kernel 1: gate_x = mean over L (warp per row) -----------
__global__ void k_gatex(const float* __restrict__ x) {
    int row  = blockIdx.x * 4 + (threadIdx.x >> 5);   // (b, c) flattened
    int lane = threadIdx.x & 31;
    const float4* xp = (const float4*)(x + (size_t)row * LIN);
    float s = 0.f;
#pragma unroll
    for (int k = 0; k < 8; ++k) {
        float4 v = xp[lane + k * 32];
        s += (v.x + v.y) + (v.z + v.w);
    }
#pragma unroll
    for (int off = 16; off; off >>= 1) s += __shfl_down_sync(0xffffffffu, s, off);
    if (lane == 0) g_gatex[row] = s * (1.0f / (float)LIN);
}

// ---------------- kernel 2: gating, top-k, loss ---------------------------
__device__ __forceinline__ float cv_sq4(const float* w) {
    float mn = 0.25f * (w[0] + w[1] + w[2] + w[3]);
    float s = 0.f;
#pragma unroll
    for (int e = 0; e < 4; ++e) { float d = w[e] - mn; s += d * d; }
    s *= (1.0f / 3.0f);                    // ddof = 1
    return s / (mn * mn + 1e-10f);
}

__global__ void k_gate(const float* __restrict__ noise,
                       const float* __restrict__ w_gate,
                       const float* __restrict__ w_noise,
                       float* __restrict__ out, int loss_idx)
{
    int b = threadIdx.x;                   // 32 threads, one per batch row
    float clean[NE] = {0.f, 0.f, 0.f, 0.f};
    float raw[NE]   = {0.f, 0.f, 0.f, 0.f};
    for (int c = 0; c < CIN; ++c) {
        float gx = g_gatex[b * CIN + c];
#pragma unroll
        for (int e = 0; e < NE; ++e) {
            clean[e] = fmaf(gx, w_gate[c * NE + e],  clean[e]);
            raw[e]   = fmaf(gx, w_noise[c * NE + e], raw[e]);
        }
    }
    float nstd[NE], noisy[NE], sm[NE];
    float m = -1e30f;
#pragma unroll
    for (int e = 0; e < NE; ++e) {
        float r  = raw[e];
        float sp = (r > 20.f) ? r : log1pf(expf(r));   // softplus
        nstd[e]  = sp + 0.01f;                          // NOISE_EPS
        noisy[e] = clean[e] + noise[b * NE + e] * nstd[e];
        m = fmaxf(m, noisy[e]);
    }
    float ssum = 0.f;
#pragma unroll
    for (int e = 0; e < NE; ++e) { sm[e] = expf(noisy[e] - m); ssum += sm[e]; }
    float inv = 1.f / ssum;
#pragma unroll
    for (int e = 0; e < NE; ++e) sm[e] *= inv;

    int   idx[4] = {0, 1, 2, 3};
    float v[4]   = {sm[0], sm[1], sm[2], sm[3]};
#pragma unroll
    for (int a = 0; a < 3; ++a)
#pragma unroll
        for (int q = a + 1; q < 4; ++q)
            if (v[q] > v[a]) {
                float tv = v[a]; v[a] = v[q]; v[q] = tv;
                int   ti = idx[a]; idx[a] = idx[q]; idx[q] = ti;
            }

    float e1 = expf(v[1] - v[0]);
    float gs = 1.f + e1;
    float g0 = 1.f / gs;
    float g1 = e1 / gs;
    g_sel [b * 2 + 0] = idx[0];  g_sel [b * 2 + 1] = idx[1];
    g_selw[b * 2 + 0] = g0;      g_selw[b * 2 + 1] = g1;

    float gates[4] = {0.f, 0.f, 0.f, 0.f};
    gates[idx[0]] = g0;
    gates[idx[1]] = g1;

    float thr_in  = v[2];
    float thr_out = v[1];
    float loadc[4];
#pragma unroll
    for (int e = 0; e < NE; ++e) {
        bool  is_in = noisy[e] > thr_in;
        float thr   = is_in ? thr_in : thr_out;
        float z     = (clean[e] - thr) / nstd[e];
        loadc[e]    = 0.5f * (1.f + erff(z * 0.70710678118654752f));
    }

    float imp[4], ld[4];
#pragma unroll
    for (int e = 0; e < NE; ++e) {
        float a = gates[e], l2 = loadc[e];
        for (int off = 16; off; off >>= 1) {
            a  += __shfl_down_sync(0xffffffffu, a,  off);
            l2 += __shfl_down_sync(0xffffffffu, l2, off);
        }
        imp[e] = a; ld[e] = l2;
    }
    if (b == 0)
        out[loss_idx] = 0.01f * (cv_sq4(imp) + cv_sq4(ld));
}

// ---------------- kernel 3: fp16 tensor-core sparse conv experts ----------
// grid: (NTILES=9, BQ=32) = 288 CTAs, 512 threads (16 warps), 1 CTA/SM.
// CTA tile: M=128 (Cout) x N=112 (l). Warp w: m-rows [(w&7)*16, +16),
// n-half (w>>3)*56. mma m16n8k16 f16, A via ldmatrix.x4, W pre-converted.
// TWO CHANNELS PER SYNC ITERATION: stage W+x for channels (c, c+1) into
// sw[0]/sw[1], one barrier pair, then 2x28 MMAs — halves the per-channel
// barrier/fill bubble ncu showed (tensor pipe 58% busy, 42% sync bubble).
// All buffer indices compile-time constants (R7 lesson).
__global__ void __launch_bounds__(512, 1)
k_conv(const float* __restrict__ x,
       const float* __restrict__ b1,
       const float* __restrict__ W2,
       const float* __restrict__ b2,
       float* __restrict__ out)
{
    __shared__ __align__(16) uint32_t sw[2][COUT * SWPAD]; // 2 channels, 36.9KB
    __shared__ uint32_t sxp[2][WNDW];                      // paired x windows
    __shared__ float sred[16][4][28];                      // epilogue partials
    __shared__ float sz[2][NTILE];
    __shared__ float ysum[2][NTILE];
    __shared__ float sW2[2][COUT];
    __shared__ float sb1[COUT];

    const int b    = blockIdx.y;
    const int l0   = blockIdx.x * NTILE;
    const int tid  = threadIdx.x;
    const int warp = tid >> 5;
    const int lane = tid & 31;
    const int g    = lane >> 2;
    const int t4   = lane & 3;
    const int m0   = (warp & 7) * 16;
    const int nhalf= warp >> 3;
    const int rlo  = m0 + g;
    const int rhi  = m0 + g + 8;
    const int so   = tid >> 4;          // W staging: o base (o = so + r*32)
    const int sq   = tid & 15;          // W staging: pair duo [2sq, 2sq+2)

    // ldmatrix per-lane base offsets into sw[0]/sw[1]
    const uint32_t a_off = ((m0 + (lane & 15)) * SWPAD + ((lane >> 4) << 2)) * 4u;
    const uint32_t a_base0 = smem_u32(&sw[0][0]) + a_off;
    const uint32_t a_base1 = smem_u32(&sw[1][0]) + a_off;

    const float* xb = x + (size_t)b * CIN * LIN;
    const bool xact = (tid < WNDW);

    if (tid < 2 * NTILE) {
        int t = tid >= NTILE;
        ysum[t][tid - t * NTILE] = 0.f;
    }

    for (int slot = 0; slot < 2; ++slot) {
        const int   e  = g_sel [b * 2 + slot];
        const float gw = g_selw[b * 2 + slot];
        const uint32_t* Whe = g_w1h + (size_t)e * (CIN * COUT * NPAIR);

        if (tid < 2 * COUT) sW2[tid >> 7][tid & 127] = W2[e * 2 * COUT + tid];
        if (tid < COUT)     sb1[tid] = b1[e * COUT + tid];

        float acc[7][4];
#pragma unroll
        for (int i = 0; i < 7; ++i)
#pragma unroll
            for (int j = 0; j < 4; ++j) acc[i][j] = 0.f;

        // prefetch registers for a channel pair (named, compile-time)
        uint2 wregA[4], wregB[4];
        float xraA = 0.f, xrbA = 0.f, xraB = 0.f, xrbB = 0.f;

        // ---- prefetch channels 0, 1 ----
#pragma unroll
        for (int r = 0; r < 4; ++r) {
            int o = so + r * 32;
            wregA[r] = *(const uint2*)(Whe + (size_t)o * NPAIR + 2 * sq);
            wregB[r] = *(const uint2*)(Whe + (size_t)(COUT * NPAIR) + (size_t)o * NPAIR + 2 * sq);
        }
        if (xact) {
            int l = l0 + tid;
            xraA = (l < LIN)     ? xb[l]           : 0.f;
            xrbA = (l + 1 < LIN) ? xb[l + 1]       : 0.f;
            xraB = (l < LIN)     ? xb[LIN + l]     : 0.f;
            xrbB = (l + 1 < LIN) ? xb[LIN + l + 1] : 0.f;
        }

        for (int c = 0; c < CIN; c += 2) {
            __syncthreads();            // prior compute done reading sw/sxp
            // stage channel pair (c, c+1): already f16x2, straight STS.64
#pragma unroll
            for (int r = 0; r < 4; ++r) {
                int o = so + r * 32;
                *(uint2*)&sw[0][o * SWPAD + sq * 2] = wregA[r];
                *(uint2*)&sw[1][o * SWPAD + sq * 2] = wregB[r];
            }
            if (xact) {
                sxp[0][tid] = pack_f16x2(xraA, xrbA);
                sxp[1][tid] = pack_f16x2(xraB, xrbB);
            }
            __syncthreads();            // staging visible

            // prefetch channels c+2, c+3 (hidden under the 56 MMAs below)
            if (c + 2 < CIN) {
                const uint32_t* WhcA = Whe + (size_t)(c + 2) * (COUT * NPAIR);
                const uint32_t* WhcB = Whe + (size_t)(c + 3) * (COUT * NPAIR);
                const float*    xcA  = xb + (size_t)(c + 2) * LIN;
                const float*    xcB  = xb + (size_t)(c + 3) * LIN;
#pragma unroll
                for (int r = 0; r < 4; ++r) {
                    int o = so + r * 32;
                    wregA[r] = *(const uint2*)(WhcA + (size_t)o * NPAIR + 2 * sq);
                    wregB[r] = *(const uint2*)(WhcB + (size_t)o * NPAIR + 2 * sq);
                }
                if (xact) {
                    int l = l0 + tid;
                    xraA = (l < LIN)     ? xcA[l]     : 0.f;
                    xrbA = (l + 1 < LIN) ? xcA[l + 1] : 0.f;
                    xraB = (l < LIN)     ? xcB[l]     : 0.f;
                    xrbB = (l + 1 < LIN) ? xcB[l + 1] : 0.f;
                }
            }

            const int bbase = nhalf * 56 + g + 2 * t4;

            // ---- channel c (buffer 0) ----
            {
                uint32_t P[14];
#pragma unroll
                for (int j = 0; j < 14; ++j) P[j] = sxp[0][bbase + 8 * j];
#pragma unroll
                for (int kk = 0; kk < 4; ++kk) {
                    uint32_t a0, a1, a2, a3;
                    asm volatile(
                        "ldmatrix.sync.aligned.m8n8.x4.shared.b16 {%0,%1,%2,%3}, [%4];"
                        : "=r"(a0), "=r"(a1), "=r"(a2), "=r"(a3)
                        : "r"(a_base0 + kk * 32));
#pragma unroll
                    for (int nb = 0; nb < 7; ++nb) {
                        int s = 2 * kk + nb;
                        mma_f16(acc[nb], a0, a1, a2, a3, P[s], P[s + 1]);
                    }
                }
            }
            // ---- channel c+1 (buffer 1) ----
            {
                uint32_t P[14];
#pragma unroll
                for (int j = 0; j < 14; ++j) P[j] = sxp[1][bbase + 8 * j];
#pragma unroll
                for (int kk = 0; kk < 4; ++kk) {
                    uint32_t a0, a1, a2, a3;
                    asm volatile(
                        "ldmatrix.sync.aligned.m8n8.x4.shared.b16 {%0,%1,%2,%3}, [%4];"
                        : "=r"(a0), "=r"(a1), "=r"(a2), "=r"(a3)
                        : "r"(a_base1 + kk * 32));
#pragma unroll
                    for (int nb = 0; nb < 7; ++nb) {
                        int s = 2 * kk + nb;
                        mma_f16(acc[nb], a0, a1, a2, a3, P[s], P[s + 1]);
                    }
                }
            }
        }

        // ---- epilogue: bias + relu + W2 partials, reduce over Cout ----
        float b1lo = sb1[rlo], b1hi = sb1[rhi];
        float w2lo0 = sW2[0][rlo], w2hi0 = sW2[0][rhi];
        float w2lo1 = sW2[1][rlo], w2hi1 = sW2[1][rhi];
        float p[28];                    // [nb*4 + r*2 + t], r = col parity
#pragma unroll
        for (int nb = 0; nb < 7; ++nb) {
            float h00 = fmaxf(acc[nb][0] + b1lo, 0.f);   // (rlo, col even)
            float h01 = fmaxf(acc[nb][1] + b1lo, 0.f);   // (rlo, col odd)
            float h10 = fmaxf(acc[nb][2] + b1hi, 0.f);   // (rhi, col even)
            float h11 = fmaxf(acc[nb][3] + b1hi, 0.f);   // (rhi, col odd)
            p[nb * 4 + 0] = fmaf(w2lo0, h00, w2hi0 * h10);
            p[nb * 4 + 1] = fmaf(w2lo1, h00, w2hi1 * h10);
            p[nb * 4 + 2] = fmaf(w2lo0, h01, w2hi0 * h11);
            p[nb * 4 + 3] = fmaf(w2lo1, h01, w2hi1 * h11);
        }
        // reduce over g (8 lanes sharing t4)
#pragma unroll
        for (int j = 0; j < 28; ++j) {
            p[j] += __shfl_down_sync(0xffffffffu, p[j], 16);
            p[j] += __shfl_down_sync(0xffffffffu, p[j], 8);
            p[j] += __shfl_down_sync(0xffffffffu, p[j], 4);
        }
        __syncthreads();                // sred free from prior use
        if (lane < 4) {
#pragma unroll
            for (int j = 0; j < 28; ++j) sred[warp][lane][j] = p[j];
        }
        __syncthreads();

        // z[t][col]: sum 8 warps of the matching n-half
        if (tid < 2 * NTILE) {
            int t   = tid >= NTILE;
            int col = tid - t * NTILE;
            int nh  = col >= 56;
            int ch  = col - nh * 56;
            int nb  = ch >> 3;
            int tt4 = (ch >> 1) & 3;
            int r   = ch & 1;
            int pj  = nb * 4 + r * 2 + t;
            float z = b2[e * 2 + t];
#pragma unroll
            for (int w8 = 0; w8 < 8; ++w8) z += sred[nh * 8 + w8][tt4][pj];
            sz[t][col] = z;
        }
        __syncthreads();

        // 2-way softmax over t, gate-weighted accumulate
        if (tid < NTILE) {
            float z0 = sz[0][tid], z1 = sz[1][tid];
            float mm = fmaxf(z0, z1);
            float a0 = expf(z0 - mm), a1 = expf(z1 - mm);
            float is = 1.f / (a0 + a1);
            ysum[0][tid] += gw * a0 * is;
            ysum[1][tid] += gw * a1 * is;
        }
        __syncthreads();
    }

    if (tid < 2 * NTILE) {
        int t = tid >= NTILE, l = tid - t * NTILE;
        int gl = l0 + l;
        if (gl < LOUT)
            out[((size_t)b * 2 + t) * LOUT + gl] = ysum[t][l];
    }
}

// ---------------- launcher ------------------------------------------------
extern "C" void kernel_launch(void* const* d_in, const int* in_sizes, int n_in,
                              void* d_out, int out_size)
{
    const float* x       = (const float*)d_in[0];
    const float* noise   = (const float*)d_in[1];
    const float* w_gate  = (const float*)d_in[2];
    const float* w_noise = (const float*)d_in[3];
    const float* W1      = (const float*)d_in[4];
    const float* b1      = (const float*)d_in[5];
    const float* W2      = (const float*)d_in[6];
    const float* b2      = (const float*)d_in[7];
    float* out = (float*)d_out;

    k_wconv<<<NE * CIN * COUT * NPAIR / 256, 256>>>(W1);
    k_gatex<<<BQ * CIN / 4, 128>>>(x);
    k_gate<<<1, 32>>>(noise, w_gate, w_noise, out, out_size - 1);
    dim3 grid(NTILES, BQ);
    k_conv<<<grid, 512>>>(x, b1, W2, b2, out);
}